// round 2
// baseline (speedup 1.0000x reference)
#include <cuda_runtime.h>
#include <math.h>

#define T_STEPS 1000
#define BATCH   16
#define MEL     80
#define HID     512
#define NCLS    64
#define NROWS   (T_STEPS*BATCH)      // 16000

#define SCAN_CTAS   64
#define COLS_PER_CTA (HID/SCAN_CTAS) // 8

// ---------------- scratch (device globals; no allocation allowed) ----------
__device__ float    g_xn0[NROWS*MEL];
__device__ float    g_be0[NROWS*HID];
__device__ float    g_xn1[NROWS*HID];
__device__ float    g_be1[NROWS*HID];
__device__ float    g_hall[NROWS*HID];
__device__ float    g_scale1[NROWS];
__device__ float    g_norm[NROWS];
__device__ float    g_err[BATCH*HID];
__device__ float    g_hzero[BATCH*HID];
__device__ unsigned g_ctr[2*T_STEPS];

// ---------------- zero scratch each graph replay ---------------------------
__global__ void zero_scratch() {
    int i = blockIdx.x*blockDim.x + threadIdx.x;
    if (i < NROWS)      g_norm[i]  = 0.f;
    if (i < 2*T_STEPS)  g_ctr[i]   = 0u;
    if (i < BATCH*HID)  g_hzero[i] = 0.f;
}

// ---------------- x_norm for cell0 input (feats) ---------------------------
// feats: (B, T, MEL). Row r = t*16+b -> g_xn0[r*MEL + k]
__global__ void xnorm0_kernel(const float* __restrict__ feats) {
    int w    = (blockIdx.x*blockDim.x + threadIdx.x) >> 5;
    int lane = threadIdx.x & 31;
    if (w >= NROWS) return;
    int t = w >> 4, b = w & 15;
    const float* row = feats + ((size_t)b*T_STEPS + t)*MEL;
    float v0 = row[lane];
    float v1 = row[lane+32];
    float v2 = (lane < MEL-64) ? row[lane+64] : 0.f;
    float s = v0*v0 + v1*v1 + v2*v2;
    #pragma unroll
    for (int off = 16; off; off >>= 1) s += __shfl_xor_sync(0xffffffffu, s, off);
    float sc  = fmaxf(sqrtf(s), 1e-6f);
    float inv = 1.f/sc;
    float* o = g_xn0 + (size_t)w*MEL;
    o[lane]    = fminf(fmaxf(v0*inv, -1.f), 1.f);
    o[lane+32] = fminf(fmaxf(v1*inv, -1.f), 1.f);
    if (lane < MEL-64) o[lane+64] = fminf(fmaxf(v2*inv, -1.f), 1.f);
}

// ---------------- x_norm + scale for cell1 input (be0) ---------------------
__global__ void xnorm1_kernel() {
    int w    = (blockIdx.x*blockDim.x + threadIdx.x) >> 5;
    int lane = threadIdx.x & 31;
    if (w >= NROWS) return;
    const float4* row = (const float4*)(g_be0 + (size_t)w*HID);
    float4 v[4];
    float s = 0.f;
    #pragma unroll
    for (int i = 0; i < 4; i++) {
        v[i] = row[lane + 32*i];
        s += v[i].x*v[i].x + v[i].y*v[i].y + v[i].z*v[i].z + v[i].w*v[i].w;
    }
    #pragma unroll
    for (int off = 16; off; off >>= 1) s += __shfl_xor_sync(0xffffffffu, s, off);
    float sc = fmaxf(sqrtf(s), 1e-6f);
    if (lane == 0) g_scale1[w] = sc;
    float inv = 1.f/sc;
    float4* o = (float4*)(g_xn1 + (size_t)w*HID);
    #pragma unroll
    for (int i = 0; i < 4; i++) {
        float4 u = v[i];
        u.x = fminf(fmaxf(u.x*inv,-1.f),1.f);
        u.y = fminf(fmaxf(u.y*inv,-1.f),1.f);
        u.z = fminf(fmaxf(u.z*inv,-1.f),1.f);
        u.w = fminf(fmaxf(u.w*inv,-1.f),1.f);
        o[lane + 32*i] = u;
    }
}

// ---------------- generic tiled SGEMM: C = A(M,K) @ W(N,K)^T ---------------
// 64x64 tile, BK=16, 256 threads, 4x4 microtile. Requires M%64==0, N%64==0, K%16==0.
__global__ __launch_bounds__(256) void sgemm_nt(
    const float* __restrict__ A, int lda,
    const float* __restrict__ W, int ldw,
    float*       __restrict__ C, int ldc,
    int K, int accumulate, const float* __restrict__ bias, int remap)
{
    __shared__ float As[16][64];
    __shared__ float Ws[16][64];
    int bm = blockIdx.y*64, bn = blockIdx.x*64;
    int tid = threadIdx.x;
    int lr  = tid >> 2;          // 0..63
    int kq  = (tid & 3)*4;       // 0,4,8,12
    int tx  = tid & 15, ty = tid >> 4;
    float acc[4][4];
    #pragma unroll
    for (int i=0;i<4;i++)
        #pragma unroll
        for (int j=0;j<4;j++) acc[i][j]=0.f;

    for (int k0 = 0; k0 < K; k0 += 16) {
        float4 av = *(const float4*)(A + (size_t)(bm+lr)*lda + k0 + kq);
        float4 wv = *(const float4*)(W + (size_t)(bn+lr)*ldw + k0 + kq);
        As[kq+0][lr]=av.x; As[kq+1][lr]=av.y; As[kq+2][lr]=av.z; As[kq+3][lr]=av.w;
        Ws[kq+0][lr]=wv.x; Ws[kq+1][lr]=wv.y; Ws[kq+2][lr]=wv.z; Ws[kq+3][lr]=wv.w;
        __syncthreads();
        #pragma unroll
        for (int k = 0; k < 16; k++) {
            float4 a4 = *(float4*)&As[k][ty*4];
            float4 w4 = *(float4*)&Ws[k][tx*4];
            float ar[4] = {a4.x, a4.y, a4.z, a4.w};
            float wr[4] = {w4.x, w4.y, w4.z, w4.w};
            #pragma unroll
            for (int i=0;i<4;i++)
                #pragma unroll
                for (int j=0;j<4;j++) acc[i][j] += ar[i]*wr[j];
        }
        __syncthreads();
    }
    #pragma unroll
    for (int i = 0; i < 4; i++) {
        int r = bm + ty*4 + i;
        int orow = remap ? ((r & 15)*T_STEPS + (r >> 4)) : r;
        #pragma unroll
        for (int j = 0; j < 4; j++) {
            int cidx = bn + tx*4 + j;
            float val = acc[i][j];
            if (bias) val += bias[cidx];
            float* p = C + (size_t)orow*ldc + cidx;
            if (accumulate) val += *p;
            *p = val;
        }
    }
}

// ---------------- grid barrier (per-instance counters, replay-safe) --------
__device__ __forceinline__ void gbar(unsigned* c) {
    __syncthreads();
    if (threadIdx.x == 0) {
        __threadfence();
        unsigned prev = atomicAdd(c, 1u);
        if (prev + 1u < SCAN_CTAS) {
            while (*((volatile unsigned*)c) < SCAN_CTAS) { }
        }
        __threadfence();
    }
    __syncthreads();
}

// ---------------- inner GEMM: 16 rows x 4 cols per warp-quadrant -----------
// Each warp covers rows [r0,r0+4) x cols [c0,c0+4); lanes split K (512) by float4.
__device__ __forceinline__ void tile_mm(const float* __restrict__ wgt,
                                        const float* __restrict__ src,
                                        int r0, int c0, int lane, float acc[16])
{
    #pragma unroll
    for (int j = 0; j < 16; j++) acc[j] = 0.f;
    #pragma unroll
    for (int i = 0; i < 4; i++) {
        int kf = (lane + 32*i)*4;
        float4 w0 = *(const float4*)&wgt[(c0+0)*HID + kf];
        float4 w1 = *(const float4*)&wgt[(c0+1)*HID + kf];
        float4 w2 = *(const float4*)&wgt[(c0+2)*HID + kf];
        float4 w3 = *(const float4*)&wgt[(c0+3)*HID + kf];
        #pragma unroll
        for (int r = 0; r < 4; r++) {
            float4 h = *(const float4*)&src[(r0+r)*HID + kf];
            acc[r*4+0] += h.x*w0.x + h.y*w0.y + h.z*w0.z + h.w*w0.w;
            acc[r*4+1] += h.x*w1.x + h.y*w1.y + h.z*w1.z + h.w*w1.w;
            acc[r*4+2] += h.x*w2.x + h.y*w2.y + h.z*w2.z + h.w*w2.w;
            acc[r*4+3] += h.x*w3.x + h.y*w3.y + h.z*w3.z + h.w*w3.w;
        }
    }
    // cross-lane (K) reduction
    #pragma unroll
    for (int off = 16; off; off >>= 1) {
        #pragma unroll
        for (int j = 0; j < 16; j++)
            acc[j] += __shfl_xor_sync(0xffffffffu, acc[j], off);
    }
}

__device__ __forceinline__ float pick16(const float acc[16], int lane) {
    float v = acc[0];
    #pragma unroll
    for (int j = 1; j < 16; j++) if (lane == j) v = acc[j];
    return v;
}

// ---------------- persistent sequential scan over T ------------------------
__global__ __launch_bounds__(256, 1) void scan_kernel(
    const float* __restrict__ C1, const float* __restrict__ W1,
    const float* __restrict__ a1, const float* __restrict__ taup,
    const float* __restrict__ gamp)
{
    extern __shared__ float sm[];
    float* wC  = sm;                           // 8*512
    float* wW  = wC + COLS_PER_CTA*HID;        // 8*512
    float* hb  = wW + COLS_PER_CTA*HID;        // 16*512  (h_{t-1}, full)
    float* eb  = hb + BATCH*HID;               // 16*512  (error, full)
    float* sga = eb + BATCH*HID;               // 8

    int g = blockIdx.x, tid = threadIdx.x;
    int mbase = g*COLS_PER_CTA;

    for (int i = tid; i < COLS_PER_CTA*HID; i += 256) {
        int mm = i >> 9, k = i & (HID-1);
        wC[i] = C1[(size_t)(mbase+mm)*HID + k];
        wW[i] = W1[(size_t)(mbase+mm)*HID + k];
    }
    if (tid < COLS_PER_CTA) sga[tid] = 1.f/(1.f + expf(-a1[mbase+tid]));
    float tau = taup[0], gam = gamp[0];
    __syncthreads();

    int warp = tid >> 5, lane = tid & 31;
    int r0 = (warp & 3)*4;        // row group (batch)
    int c0 = (warp >> 2)*4;       // col group within CTA slice

    for (int t = 0; t < T_STEPS; ++t) {
        const float* hprev = (t == 0) ? g_hzero : (g_hall + (size_t)(t-1)*BATCH*HID);
        // broadcast-load full h_{t-1} (L2, bypass L1: written by other SMs)
        {
            const float4* s4 = (const float4*)hprev;
            float4* d4 = (float4*)hb;
            for (int i = tid; i < BATCH*HID/4; i += 256) d4[i] = __ldcg(s4 + i);
        }
        __syncthreads();

        // ---- phase A: P = h @ C1^T  -> error, partial norms -----------
        float acc[16];
        tile_mm(wC, hb, r0, c0, lane, acc);
        if (lane < 16) {
            float v = pick16(acc, lane);
            int rr = lane >> 2, cc = lane & 3;
            int b = r0 + rr;
            int m = mbase + c0 + cc;
            float sc = g_scale1[(size_t)t*BATCH + b];
            float e  = g_be0[((size_t)t*BATCH + b)*HID + m] - tanhf(v)*sc;
            g_err[b*HID + m] = e;
            float s2 = e*e;
            s2 += __shfl_xor_sync(0x0000ffffu, s2, 1);
            s2 += __shfl_xor_sync(0x0000ffffu, s2, 2);
            if (cc == 0) atomicAdd(&g_norm[(size_t)t*BATCH + b], s2);
        }
        gbar(&g_ctr[2*t]);

        // ---- phase B: E = error @ W1^T -> h update --------------------
        {
            const float4* s4 = (const float4*)g_err;
            float4* d4 = (float4*)eb;
            for (int i = tid; i < BATCH*HID/4; i += 256) d4[i] = __ldcg(s4 + i);
        }
        __syncthreads();

        float acc2[16];
        tile_mm(wW, eb, r0, c0, lane, acc2);
        if (lane < 16) {
            float v = pick16(acc2, lane);
            int rr = lane >> 2, cc = lane & 3;
            int b = r0 + rr;
            int m = mbase + c0 + cc;
            float sc  = g_scale1[(size_t)t*BATCH + b];
            float ns  = __ldcg(&g_norm[(size_t)t*BATCH + b]);
            float rel = fminf(sqrtf(ns)/sc, 4.f);
            float sur = 1.f/(1.f + expf(-(rel - tau)/gam));
            float hv  = hb[b*HID + m];
            float ih  = 0.2f*hv + 0.6f*g_be1[((size_t)t*BATCH + b)*HID + m] + 0.2f*sur*v;
            float gg  = sur * sga[c0 + cc];
            float hn  = hv*(1.f - gg) + tanhf(ih)*gg;
            g_hall[((size_t)t*BATCH + b)*HID + m] = hn;
        }
        gbar(&g_ctr[2*t + 1]);
    }
}

// ---------------- launch ----------------------------------------------------
extern "C" void kernel_launch(void* const* d_in, const int* in_sizes, int n_in,
                              void* d_out, int out_size)
{
    const float* feats  = (const float*)d_in[0];
    const float* B0     = (const float*)d_in[2];
    const float* C1     = (const float*)d_in[7];
    const float* B1     = (const float*)d_in[8];
    const float* W1     = (const float*)d_in[9];
    const float* a1     = (const float*)d_in[10];
    const float* tau1   = (const float*)d_in[11];
    const float* gam1   = (const float*)d_in[12];
    const float* head_w = (const float*)d_in[13];
    const float* head_b = (const float*)d_in[14];
    float* out = (float*)d_out;

    float *p_xn0, *p_be0, *p_xn1, *p_be1, *p_hall;
    cudaGetSymbolAddress((void**)&p_xn0,  g_xn0);
    cudaGetSymbolAddress((void**)&p_be0,  g_be0);
    cudaGetSymbolAddress((void**)&p_xn1,  g_xn1);
    cudaGetSymbolAddress((void**)&p_be1,  g_be1);
    cudaGetSymbolAddress((void**)&p_hall, g_hall);

    const int SCAN_SMEM = (2*COLS_PER_CTA*HID + 2*BATCH*HID + COLS_PER_CTA)*4;
    cudaFuncSetAttribute(scan_kernel, cudaFuncAttributeMaxDynamicSharedMemorySize, SCAN_SMEM);

    zero_scratch<<<64, 256>>>();
    xnorm0_kernel<<<(NROWS*32)/256, 256>>>(feats);

    dim3 g1(HID/64, NROWS/64);
    // be0 = xn0 (16000x80) @ B0(512x80)^T
    sgemm_nt<<<g1, 256>>>(p_xn0, MEL, B0, MEL, p_be0, HID, MEL, 0, nullptr, 0);
    xnorm1_kernel<<<(NROWS*32)/256, 256>>>();
    // be1 = xn1 (16000x512) @ B1(512x512)^T
    sgemm_nt<<<g1, 256>>>(p_xn1, HID, B1, HID, p_be1, HID, HID, 0, nullptr, 0);

    scan_kernel<<<SCAN_CTAS, 256, SCAN_SMEM>>>(C1, W1, a1, tau1, gam1);

    // head: out = h_all @ head_w[:, :512]^T + be1 @ head_w[:, 512:]^T + head_b
    dim3 gh(NCLS/64, NROWS/64);
    sgemm_nt<<<gh, 256>>>(p_hall, HID, head_w,       2*HID, out, NCLS, HID, 0, nullptr, 1);
    sgemm_nt<<<gh, 256>>>(p_be1,  HID, head_w + HID, 2*HID, out, NCLS, HID, 1, head_b, 1);
}